// round 1
// baseline (speedup 1.0000x reference)
#include <cuda_runtime.h>
#include <cuda_bf16.h>
#include <math.h>

// ---------------- problem constants ----------------
#define BB 64
#define NN 512
#define RR 1024
#define EE 1024
#define KTOP 256
#define BR (BB*RR)          // 65536

// ---------------- device scratch (no allocations allowed) ----------------
__device__ float g_bufA[(long)BB*NN*RR];   // 134MB: masked GE, later X2, X3
__device__ float g_bufB[(long)BB*NN*RR];   // E1, later Y0, X2...
__device__ float g_bufC[(long)BB*NN*RR];   // E2, later X1, Y2
__device__ float g_adj [(long)BB*NN*NN];   // 67MB
__device__ float g_xcat[BB*3072];
__device__ float g_gates[BB*4096];
__device__ float g_gates2[BB*4096];
__device__ float g_hterm1[BB*RR];
__device__ float g_hterm2[BB*RR];
__device__ float g_pvec[BB*RR];
__device__ float g_srow[BB*NN];
__device__ float g_dvec[BB*NN];
__device__ float g_minv[BB];
__device__ float g_attv[BB*RR];
__device__ float g_xl[BB*2048];
__device__ float g_hatt[BR];
__device__ float g_catt[BR];
__device__ float g_hlang[BR];
__device__ float g_clang[BR];

// ---------------- generic tiled GEMM ----------------
// C[M,N] = A[M,K] @ op(B) (+ epilogue), op(B)=B^T if BT (B is [N,K]) else B [K,N].
// All of M%BM==0, N%BN==0, K%BK==0 guaranteed by construction.
template<int BM,int BN,int BK,int TM,int TN,bool BT>
__global__ void __launch_bounds__(256) gemm_kernel(
    const float* __restrict__ A,int lda,long sA,
    const float* __restrict__ B,int ldb,long sB,
    float* __restrict__ C,int ldc,long sC,
    int K,
    const float* __restrict__ bias,
    const float* __restrict__ addv,int addv_ld,int addv_shift,
    const float* __restrict__ rs,const float* __restrict__ ps,
    int relu,int accum)
{
    __shared__ float As[BK][BM];
    __shared__ float Bs[BK][BN];
    const int tid = threadIdx.x;
    const float* Ab = A + blockIdx.z * sA;
    const float* Bb = B + blockIdx.z * sB;
    float* Cb = C + blockIdx.z * sC;
    const int rowBase = blockIdx.y * BM;
    const int colBase = blockIdx.x * BN;
    const int tx = tid % (BN/TN);
    const int ty = tid / (BN/TN);

    float acc[TM][TN];
#pragma unroll
    for (int i=0;i<TM;i++)
#pragma unroll
        for (int j=0;j<TN;j++) acc[i][j]=0.f;

    for (int k0=0;k0<K;k0+=BK) {
        // A tile -> As[k][m]
#pragma unroll
        for (int i=tid*4;i<BM*BK;i+=256*4) {
            int r=i/BK, kk=i%BK;
            float4 v = *(const float4*)(Ab + (long)(rowBase+r)*lda + k0 + kk);
            As[kk+0][r]=v.x; As[kk+1][r]=v.y; As[kk+2][r]=v.z; As[kk+3][r]=v.w;
        }
        if (BT) {
#pragma unroll
            for (int i=tid*4;i<BN*BK;i+=256*4) {
                int r=i/BK, kk=i%BK;
                float4 v = *(const float4*)(Bb + (long)(colBase+r)*ldb + k0 + kk);
                Bs[kk+0][r]=v.x; Bs[kk+1][r]=v.y; Bs[kk+2][r]=v.z; Bs[kk+3][r]=v.w;
            }
        } else {
#pragma unroll
            for (int i=tid*4;i<BK*BN;i+=256*4) {
                int r=i/BN, cc=i%BN;
                *(float4*)&Bs[r][cc] = *(const float4*)(Bb + (long)(k0+r)*ldb + colBase + cc);
            }
        }
        __syncthreads();
#pragma unroll
        for (int k=0;k<BK;k++) {
            float a[TM], b[TN];
#pragma unroll
            for (int i=0;i<TM;i+=4) *(float4*)&a[i] = *(const float4*)&As[k][ty*TM+i];
#pragma unroll
            for (int j=0;j<TN;j+=4) *(float4*)&b[j] = *(const float4*)&Bs[k][tx*TN+j];
#pragma unroll
            for (int i=0;i<TM;i++)
#pragma unroll
                for (int j=0;j<TN;j++) acc[i][j] = fmaf(a[i], b[j], acc[i][j]);
        }
        __syncthreads();
    }

    const int vb = rowBase >> addv_shift;  // rows of a tile never straddle a batch
#pragma unroll
    for (int i=0;i<TM;i++) {
        int r = rowBase + ty*TM + i;
        float rsv = rs ? rs[r] : 1.f;
        float psv = ps ? ps[r] : 1.f;
#pragma unroll
        for (int j=0;j<TN;j++) {
            int c = colBase + tx*TN + j;
            float v = acc[i][j];
            if (addv)  v += rsv * addv[(long)vb*addv_ld + c];
            if (bias)  v += bias[c];
            if (accum) v += Cb[(long)r*ldc + c];
            if (relu)  v = fmaxf(v, 0.f);
            if (ps)    v *= psv;
            Cb[(long)r*ldc + c] = v;
        }
    }
}

template<int BM,int BN,int BK,int TM,int TN,bool BT>
static void launch_gemm(const float* A,int lda,long sA,const float* B,int ldb,long sB,
                        float* C,int ldc,long sC,int M,int N,int K,int batch,
                        const float* bias=nullptr,const float* addv=nullptr,int addv_ld=1,int addv_shift=0,
                        const float* rs=nullptr,const float* ps=nullptr,int relu=0,int accum=0)
{
    dim3 g(N/BN, M/BM, batch);
    gemm_kernel<BM,BN,BK,TM,TN,BT><<<g,256>>>(A,lda,sA,B,ldb,sB,C,ldc,sC,K,
                                              bias,addv,addv_ld,addv_shift,rs,ps,relu,accum);
}

// ---------------- pointwise / reduction kernels ----------------
__device__ __forceinline__ float sigm(float x){ return 1.f/(1.f+__expf(-x)); }

__global__ void concat3_kernel(const float* a,const float* b,const float* c,float* out){
    int idx = blockIdx.x*blockDim.x+threadIdx.x;
    if (idx >= BB*3072) return;
    int bb = idx/3072, j = idx%3072;
    float v;
    if (j < 1024) v = a[bb*1024 + j];
    else if (j < 2048) v = b[bb*1024 + (j-1024)];
    else v = c[bb*1024 + (j-2048)];
    out[idx] = v;
}

__global__ void concat2_kernel(const float* a,const float* b,float* out){
    int idx = blockIdx.x*blockDim.x+threadIdx.x;
    if (idx >= BB*2048) return;
    int bb = idx/2048, j = idx%2048;
    out[idx] = (j<1024) ? a[bb*1024+j] : b[bb*1024+(j-1024)];
}

__global__ void lstm_kernel(const float* gates,const float* c_prev,
                            float* h_out,float* c_out){
    int idx = blockIdx.x*blockDim.x+threadIdx.x;
    if (idx >= BR) return;
    int bb = idx >> 10, r = idx & 1023;
    const float* g = gates + bb*4096;
    float ig = sigm(g[r]);
    float fg = sigm(g[1024+r]);
    float gg = tanhf(g[2048+r]);
    float og = sigm(g[3072+r]);
    float c = fg * c_prev[idx] + ig * gg;
    h_out[idx] = og * tanhf(c);
    c_out[idx] = c;
}

__global__ void maskmul_kernel(const float* ge,const float* mask,float* gem){
    long i = (long)blockIdx.x*blockDim.x+threadIdx.x;   // float4 index
    long total = (long)BB*NN*RR/4;
    if (i >= total) return;
    int row = (int)(i >> 8);                             // 256 float4 per 1024-row
    float m = mask[row];
    float4 v = ((const float4*)ge)[i];
    v.x*=m; v.y*=m; v.z*=m; v.w*=m;
    ((float4*)gem)[i] = v;
}

__global__ void batchmin_kernel(const float* Adj,float* minv){
    __shared__ float sm[1024];
    const float* a = Adj + (long)blockIdx.x*NN*NN;
    float mn = INFINITY;
    for (int i=threadIdx.x;i<NN*NN;i+=1024) mn = fminf(mn, a[i]);
    sm[threadIdx.x]=mn; __syncthreads();
    for (int s=512;s>0;s>>=1){ if (threadIdx.x<s) sm[threadIdx.x]=fminf(sm[threadIdx.x],sm[threadIdx.x+s]); __syncthreads(); }
    if (threadIdx.x==0) minv[blockIdx.x]=sm[0];
}

// Per row: v=(Adj-min)*m_row (>=0), exact top-256 (lax.top_k tie semantics:
// equal values -> lower index first), write kept back, zero rest, and emit
// d = rowsum^{-1/2} (0 if rowsum==0).
__global__ void __launch_bounds__(512) topk_kernel(float* Adj,const float* minv,
                                                   const float* mask,float* dvec){
    __shared__ unsigned long long keys[NN];
    __shared__ float red[NN];
    int row = blockIdx.x;
    int t = threadIdx.x;
    int bb = row >> 9;
    float mrow = mask[row];
    float* arow = Adj + (long)row*NN;
    float v = (arow[t] - minv[bb]) * mrow;               // >= 0
    keys[t] = ((unsigned long long)__float_as_uint(v) << 32) | (unsigned)(NN-1-t);
    __syncthreads();
    // bitonic sort descending (ties: larger low-bits = smaller index first)
    for (unsigned k2=2;k2<=NN;k2<<=1)
        for (unsigned j=k2>>1;j>0;j>>=1){
            unsigned ixj = t ^ j;
            if (ixj > (unsigned)t){
                unsigned long long x=keys[t], y=keys[ixj];
                bool desc = ((t & k2) == 0);
                if (desc ? (x<y) : (x>y)){ keys[t]=y; keys[ixj]=x; }
            }
            __syncthreads();
        }
    unsigned long long kk = keys[t];
    arow[t] = 0.f;
    __syncthreads();
    float s = 0.f;
    if (t < KTOP){
        int col = (NN-1) - (int)(unsigned)(kk & 0xffffffffu);
        float val = __uint_as_float((unsigned)(kk >> 32));
        arow[col] = val;
        s = val;
    }
    red[t]=s; __syncthreads();
    for (int st=NN/2;st>0;st>>=1){ if (t<st) red[t]+=red[t+st]; __syncthreads(); }
    if (t==0) dvec[row] = (red[0] > 0.f) ? rsqrtf(red[0]) : 0.f;
}

__global__ void dscale_kernel(float* Adj,const float* d){
    long idx = (long)blockIdx.x*blockDim.x+threadIdx.x;
    if (idx >= (long)BB*NN*NN) return;
    int row = (int)(idx >> 9);
    int col = (int)(idx & (NN-1));
    int bb = row >> 9;
    Adj[idx] *= d[row] * d[(bb<<9)+col];
}

__global__ void srow_kernel(const float* Adj,const float* mask,float* srow){
    int warp = (blockIdx.x*blockDim.x+threadIdx.x) >> 5;
    int lane = threadIdx.x & 31;
    if (warp >= BB*NN) return;
    int bb = warp >> 9;
    const float* a = Adj + (long)warp*NN;
    const float* m = mask + bb*NN;
    float s = 0.f;
    for (int k=lane;k<NN;k+=32) s += a[k]*m[k];
    for (int o=16;o;o>>=1) s += __shfl_xor_sync(0xffffffffu, s, o);
    if (lane==0) srow[warp] = s;
}

__global__ void colmax_kernel(const float* X,float* att){
    int idx = blockIdx.x*blockDim.x+threadIdx.x;
    if (idx >= BB*RR) return;
    int bb = idx >> 10, j = idx & 1023;
    const float* x = X + (long)bb*NN*RR + j;
    float mx = -INFINITY;
    for (int n=0;n<NN;n++) mx = fmaxf(mx, x[(long)n*RR]);
    att[idx] = mx;
}

__global__ void pack_kernel(const float* hatt,const float* catt,
                            const float* hlang,const float* clang,
                            float* out,int out_size){
    int i = blockIdx.x*blockDim.x+threadIdx.x;
    if (i >= BR) return;
    out[i] = hlang[i];
    if (out_size >= 5*BR){
        out[1*BR+i] = hatt[i];
        out[2*BR+i] = hlang[i];
        out[3*BR+i] = catt[i];
        out[4*BR+i] = clang[i];
    }
}

// ---------------- host driver ----------------
extern "C" void kernel_launch(void* const* d_in, const int* in_sizes, int n_in,
                              void* d_out, int out_size)
{
    const float* xt      = (const float*)d_in[0];
    const float* fc      = (const float*)d_in[1];
    const float* ge      = (const float*)d_in[2];
    const float* sh      = (const float*)d_in[4];   // (2,B,R)
    const float* sc      = (const float*)d_in[5];
    const float* mask    = (const float*)d_in[6];   // (B,N)
    const float* aWih    = (const float*)d_in[7];   // (4096,3072)
    const float* aWhh    = (const float*)d_in[8];   // (4096,1024)
    const float* abih    = (const float*)d_in[9];
    const float* abhh    = (const float*)d_in[10];
    const float* lWih    = (const float*)d_in[11];  // (4096,2048)
    const float* lWhh    = (const float*)d_in[12];
    const float* lbih    = (const float*)d_in[13];
    const float* lbhh    = (const float*)d_in[14];
    const float* e1W     = (const float*)d_in[15];  // (1024,2048)
    const float* e1b     = (const float*)d_in[16];
    const float* e2W     = (const float*)d_in[17];
    const float* e2b     = (const float*)d_in[18];
    const float* gW0     = (const float*)d_in[19];  // (2048,1024)
    const float* gb0     = (const float*)d_in[20];
    const float* gW1     = (const float*)d_in[21];  // (1024,1024)
    const float* gb1     = (const float*)d_in[22];
    const float* gW2     = (const float*)d_in[23];
    const float* gb2     = (const float*)d_in[24];
    (void)in_sizes; (void)n_in;
    float* out = (float*)d_out;

    static float *bufA=nullptr,*bufB=nullptr,*bufC=nullptr,*adj=nullptr,*xcat=nullptr,
                 *gates=nullptr,*gates2=nullptr,*ht1=nullptr,*ht2=nullptr,*pvec=nullptr,
                 *srow=nullptr,*dvec=nullptr,*minv=nullptr,*attv=nullptr,*xl=nullptr,
                 *hatt=nullptr,*catt=nullptr,*hlang=nullptr,*clang=nullptr;
    if (!bufA){
        cudaGetSymbolAddress((void**)&bufA,  g_bufA);
        cudaGetSymbolAddress((void**)&bufB,  g_bufB);
        cudaGetSymbolAddress((void**)&bufC,  g_bufC);
        cudaGetSymbolAddress((void**)&adj,   g_adj);
        cudaGetSymbolAddress((void**)&xcat,  g_xcat);
        cudaGetSymbolAddress((void**)&gates, g_gates);
        cudaGetSymbolAddress((void**)&gates2,g_gates2);
        cudaGetSymbolAddress((void**)&ht1,   g_hterm1);
        cudaGetSymbolAddress((void**)&ht2,   g_hterm2);
        cudaGetSymbolAddress((void**)&pvec,  g_pvec);
        cudaGetSymbolAddress((void**)&srow,  g_srow);
        cudaGetSymbolAddress((void**)&dvec,  g_dvec);
        cudaGetSymbolAddress((void**)&minv,  g_minv);
        cudaGetSymbolAddress((void**)&attv,  g_attv);
        cudaGetSymbolAddress((void**)&xl,    g_xl);
        cudaGetSymbolAddress((void**)&hatt,  g_hatt);
        cudaGetSymbolAddress((void**)&catt,  g_catt);
        cudaGetSymbolAddress((void**)&hlang, g_hlang);
        cudaGetSymbolAddress((void**)&clang, g_clang);
    }

    const float* prev_h = sh + BR;   // state_h[1]
    const float* h0     = sh;        // state_h[0]
    const float* c0     = sc;
    const float* c1     = sc + BR;

    // ---- attention LSTM ----
    concat3_kernel<<<(BB*3072+255)/256,256>>>(prev_h, fc, xt, xcat);
    launch_gemm<64,64,16,4,4,true >(xcat,3072,0, aWih,3072,0, gates,4096,0, BB,4096,3072,1, abih);
    launch_gemm<64,64,16,4,4,true >(h0,1024,0,   aWhh,1024,0, gates,4096,0, BB,4096,1024,1, abhh,
                                    nullptr,1,0,nullptr,nullptr,0,/*accum=*/1);
    lstm_kernel<<<(BR+255)/256,256>>>(gates, c0, hatt, catt);

    // ---- masked graph embedding ----
    maskmul_kernel<<<(int)(((long)BB*NN*RR/4+255)/256),256>>>(ge, mask, bufA);

    // ---- e1 / e2 (split concat: (m*GE)@Wa^T + m*(h_att@Wb^T) + b) ----
    launch_gemm<64,64,16,4,4,true >(hatt,1024,0, e1W+1024,2048,0, ht1,1024,0, BB,1024,1024,1);
    launch_gemm<64,64,16,4,4,true >(hatt,1024,0, e2W+1024,2048,0, ht2,1024,0, BB,1024,1024,1);
    launch_gemm<128,128,16,8,8,true>(bufA,1024,0, e1W,2048,0, bufB,1024,0, BB*NN,1024,1024,1,
                                     e1b, ht1,1024,9, mask);
    launch_gemm<128,128,16,8,8,true>(bufA,1024,0, e2W,2048,0, bufC,1024,0, BB*NN,1024,1024,1,
                                     e2b, ht2,1024,9, mask);

    // ---- Adj = e1 @ e2^T (batched) ----
    launch_gemm<128,128,16,8,8,true>(bufB,1024,(long)NN*RR, bufC,1024,(long)NN*RR,
                                     adj,NN,(long)NN*NN, NN,NN,1024,BB);

    // ---- min-shift, mask, exact top-K, d = rowsum^-1/2 ----
    batchmin_kernel<<<BB,1024>>>(adj, minv);
    topk_kernel<<<BB*NN,512>>>(adj, minv, mask, dvec);
    dscale_kernel<<<(int)(((long)BB*NN*NN+255)/256),256>>>(adj, dvec);

    // ---- GCN layer 0 (split concat trick) ----
    srow_kernel<<<(BB*NN*32+255)/256,256>>>(adj, mask, srow);
    launch_gemm<64,64,16,4,4,false>(prev_h,1024,0, gW0+1024*1024,1024,0, pvec,1024,0, BB,1024,1024,1);
    // Y0 = Adj @ GEM  (batched)
    launch_gemm<128,128,16,8,8,false>(adj,NN,(long)NN*NN, bufA,1024,(long)NN*RR,
                                      bufB,1024,(long)NN*RR, NN,1024,NN,BB);
    // X1 = relu(Y0@W0a + srow*pvec + b0) * m
    launch_gemm<128,128,16,8,8,false>(bufB,1024,0, gW0,1024,0, bufC,1024,0, BB*NN,1024,1024,1,
                                      gb0, pvec,1024,9, srow, mask, /*relu=*/1);

    // ---- GCN layer 1 ----
    launch_gemm<128,128,16,8,8,false>(adj,NN,(long)NN*NN, bufC,1024,(long)NN*RR,
                                      bufA,1024,(long)NN*RR, NN,1024,NN,BB);
    launch_gemm<128,128,16,8,8,false>(bufA,1024,0, gW1,1024,0, bufB,1024,0, BB*NN,1024,1024,1,
                                      gb1, nullptr,1,0, nullptr, mask, /*relu=*/1);

    // ---- GCN layer 2 ----
    launch_gemm<128,128,16,8,8,false>(adj,NN,(long)NN*NN, bufB,1024,(long)NN*RR,
                                      bufC,1024,(long)NN*RR, NN,1024,NN,BB);
    launch_gemm<128,128,16,8,8,false>(bufC,1024,0, gW2,1024,0, bufA,1024,0, BB*NN,1024,1024,1,
                                      gb2, nullptr,1,0, nullptr, mask, /*relu=*/1);

    // ---- att = max over N ----
    colmax_kernel<<<(BB*RR+255)/256,256>>>(bufA, attv);

    // ---- language LSTM ----
    concat2_kernel<<<(BB*2048+255)/256,256>>>(attv, hatt, xl);
    launch_gemm<64,64,16,4,4,true >(xl,2048,0, lWih,2048,0, gates2,4096,0, BB,4096,2048,1, lbih);
    launch_gemm<64,64,16,4,4,true >(prev_h,1024,0, lWhh,1024,0, gates2,4096,0, BB,4096,1024,1, lbhh,
                                    nullptr,1,0,nullptr,nullptr,0,/*accum=*/1);
    lstm_kernel<<<(BR+255)/256,256>>>(gates2, c1, hlang, clang);

    // ---- pack outputs: (output, stack[h_att,h_lang], stack[c_att,c_lang]) ----
    pack_kernel<<<(BR+255)/256,256>>>(hatt, catt, hlang, clang, out, out_size);
}